// round 11
// baseline (speedup 1.0000x reference)
#include <cuda_runtime.h>
#include <cuda_bf16.h>
#include <cstdint>

namespace cfg {
constexpr int B = 8, T = 2048, C = 512;
constexpr int BT = B * T;  // 16384
}

// ---------------- scratch (static device arrays; no allocation) ----------------
__device__ __align__(128) __nv_bfloat16 g_X[2 * cfg::BT * cfg::C];       // [xl, xr]
__device__ __align__(128) __nv_bfloat16 g_w16[6 * cfg::C * cfg::C];      // lp1,rp1,lp2,rp2,lp3,rp3
__device__ __align__(128) __nv_bfloat16 g_h[4 * cfg::BT * cfg::C];       // proj outputs
__device__ __align__(128) __nv_bfloat16 g_Q[2 * cfg::BT * cfg::C];       // [Ql, Qr]
__device__ __align__(128) __nv_bfloat16 g_VT[2 * cfg::B * cfg::C * cfg::T]; // [VrT, VlT]
__device__ __align__(128) __nv_bfloat16 g_S [(size_t)cfg::B * cfg::T * cfg::T];
__device__ __align__(128) __nv_bfloat16 g_S2[(size_t)cfg::B * cfg::T * cfg::T];
__device__ __align__(128) __nv_bfloat16 g_P [2 * (size_t)cfg::B * cfg::T * cfg::T]; // [P1, P2]
__device__ __align__(128) __nv_bfloat16 g_F [2 * cfg::BT * cfg::C];      // [F1, F2]

struct P4 { const float* p[4]; };
struct DW2 { const float* w2[2]; const float* b2[2]; };

// ---------------- helpers ----------------
__device__ __forceinline__ uint32_t smem_u32(const void* p) {
    uint32_t a;
    asm("{ .reg .u64 t; cvta.to.shared.u64 t, %1; cvt.u32.u64 %0, t; }" : "=r"(a) : "l"(p));
    return a;
}

#define CP_ASYNC16(dst, src) \
    asm volatile("cp.async.cg.shared.global [%0], [%1], 16;" :: "r"(dst), "l"(src) : "memory")
#define CP_COMMIT() asm volatile("cp.async.commit_group;" ::: "memory")
#define CP_WAIT(n)  asm volatile("cp.async.wait_group %0;" :: "n"(n) : "memory")

#define LDSM4(r, addr) \
    asm volatile("ldmatrix.sync.aligned.m8n8.x4.shared.b16 {%0,%1,%2,%3}, [%4];" \
        : "=r"((r)[0]), "=r"((r)[1]), "=r"((r)[2]), "=r"((r)[3]) : "r"(addr))

#define MMA16816(c, a, b0, b1) \
    asm volatile("mma.sync.aligned.m16n8k16.row.col.f32.bf16.bf16.f32 " \
        "{%0,%1,%2,%3}, {%4,%5,%6,%7}, {%8,%9}, {%0,%1,%2,%3};" \
        : "+f"((c)[0]), "+f"((c)[1]), "+f"((c)[2]), "+f"((c)[3]) \
        : "r"((a)[0]), "r"((a)[1]), "r"((a)[2]), "r"((a)[3]), "r"(b0), "r"(b1))

#define SW128(o) ((o) ^ (((o) >> 3) & 0x70))

union BF8 { uint4 u; __nv_bfloat162 h2[4]; };

// ---------------- bf16 mma.sync GEMM: BM=128, BN=64, BK=64, NS=3, 3 CTAs/SM ----------------
// warp grid 4(m) x 2(n), warp tile 32x32; acc = 32 regs/thread.
// MODE 0: bf16 out = acc*scale (+bias); MODE 1: fp32 out +bias+res; MODE 2: dual store (row + transposed)
template <int MODE>
__global__ __launch_bounds__(256, 3)
void k_gemmB(const __nv_bfloat16* __restrict__ A,
             const __nv_bfloat16* __restrict__ Bm,
             void* __restrict__ Cout, void* __restrict__ C2,
             P4 bias, P4 res,
             int K, int lda, int ldb, int ldc,
             long long sA, long long sB, long long sC,
             int zAmask, float scale) {
    constexpr int NS = 3;
    constexpr int STAGE = (128 + 64) * 128;    // A 16KB + B 8KB = 24576
    extern __shared__ __align__(16) char dyn_raw[];
    const uint32_t sbase = smem_u32(dyn_raw);

    const int tid = threadIdx.x;
    const int lane = tid & 31, w = tid >> 5;
    const int wm = w & 3, wn = w >> 2;         // 4 m-warps x 2 n-warps; warp tile 32x32
    const int m0 = blockIdx.y * 128;
    const int n0 = blockIdx.x * 64;
    const int bz = blockIdx.z;
    A  += (size_t)(bz & zAmask) * sA;
    Bm += (size_t)bz * sB;

    const int nk = K >> 6;

    auto issue = [&](int kc, int s) {
        const uint32_t aB = sbase + s * STAGE;
        const uint32_t bB = aB + 16384;
        const __nv_bfloat16* Ag = A + (size_t)kc * 64;
        const __nv_bfloat16* Bg = Bm + (size_t)kc * 64;
#pragma unroll
        for (int i = 0; i < 4; i++) {
            int slot = tid + i * 256;
            int row = slot >> 3, v = slot & 7;          // 128 rows x 8 x 16B
            CP_ASYNC16(aB + SW128(row * 128 + v * 16),
                       (const void*)(Ag + (size_t)(m0 + row) * lda + v * 8));
        }
#pragma unroll
        for (int i = 0; i < 2; i++) {
            int slot = tid + i * 256;
            int row = slot >> 3, v = slot & 7;          // 64 rows x 8 x 16B
            CP_ASYNC16(bB + SW128(row * 128 + v * 16),
                       (const void*)(Bg + (size_t)(n0 + row) * ldb + v * 8));
        }
    };

    const uint32_t sxor = (uint32_t)(lane & 7) << 4;
    const uint32_t a_row = wm * 32 + (lane & 15);
    const uint32_t a_bc0 = (uint32_t)(lane >> 4) * 16;
    const uint32_t b_row = wn * 32 + (lane & 7) + ((lane >> 4) << 3);
    const uint32_t b_bc0 = (uint32_t)((lane >> 3) & 1) * 16;

    float acc[2][4][4];
#pragma unroll
    for (int mi = 0; mi < 2; mi++)
#pragma unroll
        for (int nj = 0; nj < 4; nj++)
#pragma unroll
            for (int e = 0; e < 4; e++) acc[mi][nj][e] = 0.f;

#pragma unroll
    for (int p = 0; p < NS - 1; p++) { issue(p, p); CP_COMMIT(); }
    CP_WAIT(NS - 2);
    __syncthreads();

    for (int kb = 0; kb < nk; kb++) {
        if (kb + NS - 1 < nk) issue(kb + NS - 1, (kb + NS - 1) % NS);
        CP_COMMIT();

        const uint32_t aB = sbase + (kb % NS) * STAGE;
        const uint32_t bB = aB + 16384;
#pragma unroll
        for (int ks = 0; ks < 4; ks++) {
            uint32_t af[2][4], bf[2][4];
            const uint32_t abc = ((uint32_t)ks * 32 + a_bc0) ^ sxor;
            const uint32_t bbc = ((uint32_t)ks * 32 + b_bc0) ^ sxor;
#pragma unroll
            for (int mi = 0; mi < 2; mi++)
                LDSM4(af[mi], aB + (a_row + mi * 16) * 128 + abc);
#pragma unroll
            for (int nb = 0; nb < 2; nb++)
                LDSM4(bf[nb], bB + (b_row + nb * 16) * 128 + bbc);
#pragma unroll
            for (int mi = 0; mi < 2; mi++)
#pragma unroll
                for (int nj = 0; nj < 4; nj++)
                    MMA16816(acc[mi][nj], af[mi], bf[nj >> 1][(nj & 1) * 2], bf[nj >> 1][(nj & 1) * 2 + 1]);
        }
        CP_WAIT(NS - 2);
        __syncthreads();
    }

    const size_t cb = (size_t)bz * sC;

    if constexpr (MODE == 2) { CP_WAIT(0); __syncthreads(); }
    unsigned short* sst = reinterpret_cast<unsigned short*>(dyn_raw);   // [128][72] bf16 staging

    const float* bp = bias.p[bz & 3];
    const float* rp = res.p[bz & 3];

#pragma unroll
    for (int mi = 0; mi < 2; mi++) {
        const int r0 = m0 + wm * 32 + mi * 16 + (lane >> 2);
        const int rl = wm * 32 + mi * 16 + (lane >> 2);
#pragma unroll
        for (int nj = 0; nj < 4; nj++) {
            const int c = n0 + wn * 32 + nj * 8 + (lane & 3) * 2;
            const int cl = wn * 32 + nj * 8 + (lane & 3) * 2;
            float v0 = acc[mi][nj][0] * scale, v1 = acc[mi][nj][1] * scale;
            float v2 = acc[mi][nj][2] * scale, v3 = acc[mi][nj][3] * scale;
            if constexpr (MODE == 0) {
                if (bp) {
                    float b0 = bp[c], b1 = bp[c + 1];
                    v0 += b0; v1 += b1; v2 += b0; v3 += b1;
                }
                __nv_bfloat16* O = (__nv_bfloat16*)Cout;
                *reinterpret_cast<__nv_bfloat162*>(&O[cb + (size_t)r0 * ldc + c]) =
                    __floats2bfloat162_rn(v0, v1);
                *reinterpret_cast<__nv_bfloat162*>(&O[cb + (size_t)(r0 + 8) * ldc + c]) =
                    __floats2bfloat162_rn(v2, v3);
            } else if constexpr (MODE == 1) {
                float b0 = bp[c], b1 = bp[c + 1];
                float* O = (float*)Cout;
                size_t o1 = cb + (size_t)r0 * ldc + c;
                size_t o2 = cb + (size_t)(r0 + 8) * ldc + c;
                float2 r1 = *reinterpret_cast<const float2*>(&rp[(size_t)r0 * ldc + c]);
                float2 r2 = *reinterpret_cast<const float2*>(&rp[(size_t)(r0 + 8) * ldc + c]);
                *reinterpret_cast<float2*>(&O[o1]) = make_float2(v0 + b0 + r1.x, v1 + b1 + r1.y);
                *reinterpret_cast<float2*>(&O[o2]) = make_float2(v2 + b0 + r2.x, v3 + b1 + r2.y);
            } else {  // MODE 2
                __nv_bfloat16* O = (__nv_bfloat16*)Cout;
                __nv_bfloat162 p1 = __floats2bfloat162_rn(v0, v1);
                __nv_bfloat162 p2 = __floats2bfloat162_rn(v2, v3);
                *reinterpret_cast<__nv_bfloat162*>(&O[cb + (size_t)r0 * ldc + c]) = p1;
                *reinterpret_cast<__nv_bfloat162*>(&O[cb + (size_t)(r0 + 8) * ldc + c]) = p2;
                *reinterpret_cast<__nv_bfloat162*>(&sst[rl * 72 + cl]) = p1;
                *reinterpret_cast<__nv_bfloat162*>(&sst[(rl + 8) * 72 + cl]) = p2;
            }
        }
    }

    if constexpr (MODE == 2) {
        __syncthreads();
        __nv_bfloat16* O2 = (__nv_bfloat16*)C2;
        // 64 n-rows x 16 chunks of 8 m = 1024 slots / 256 threads = 4 iters
#pragma unroll
        for (int it = 0; it < 4; it++) {
            const int slot = it * 256 + tid;
            const int nn = slot >> 4;
            const int mm = (slot & 15) * 8;
            unsigned short u[8];
#pragma unroll
            for (int j = 0; j < 8; j++) u[j] = sst[(mm + j) * 72 + nn];
            uint4 o;
            o.x = u[0] | ((uint32_t)u[1] << 16);
            o.y = u[2] | ((uint32_t)u[3] << 16);
            o.z = u[4] | ((uint32_t)u[5] << 16);
            o.w = u[6] | ((uint32_t)u[7] << 16);
            *reinterpret_cast<uint4*>(&O2[cb + (size_t)(n0 + nn) * ldc + m0 + mm]) = o;
        }
    }
}

// ---------------- elementwise / conversion kernels ----------------
__global__ void k_f2bf_x(const float* __restrict__ xl, const float* __restrict__ xr,
                         __nv_bfloat16* __restrict__ out, int n4) {
    int i = blockIdx.x * blockDim.x + threadIdx.x;
    if (i < 2 * n4) {
        const float* s = (i < n4) ? xl : xr;
        int off = (i < n4) ? i : i - n4;
        float4 f = reinterpret_cast<const float4*>(s)[off];
        __nv_bfloat162* o = reinterpret_cast<__nv_bfloat162*>(out) + 2 * (size_t)i;
        o[0] = __floats2bfloat162_rn(f.x, f.y);
        o[1] = __floats2bfloat162_rn(f.z, f.w);
    }
}

__global__ void k_f2bf6(const float* s0, const float* s1, const float* s2,
                        const float* s3, const float* s4, const float* s5,
                        __nv_bfloat16* __restrict__ out) {
    int i = blockIdx.x * blockDim.x + threadIdx.x;
    int which = i >> 16, off = i & 65535;
    const float* s = which == 0 ? s0 : which == 1 ? s1 : which == 2 ? s2
                    : which == 3 ? s3 : which == 4 ? s4 : s5;
    float4 f = reinterpret_cast<const float4*>(s)[off];
    __nv_bfloat162* o = reinterpret_cast<__nv_bfloat162*>(out + ((size_t)which << 18));
    o[2 * off]     = __floats2bfloat162_rn(f.x, f.y);
    o[2 * off + 1] = __floats2bfloat162_rn(f.z, f.w);
}

// depthwise conv k=3: 8 channels x 4 t-positions per thread (sliding window)
__global__ void k_dwconv(const __nv_bfloat16* __restrict__ hbase,
                         __nv_bfloat16* __restrict__ qbase, DW2 dw) {
    const int side = blockIdx.y;
    const __nv_bfloat16* h = hbase + (size_t)side * cfg::BT * cfg::C;
    __nv_bfloat16* out = qbase + (size_t)side * cfg::BT * cfg::C;
    const float* w2 = dw.w2[side];
    const float* b2 = dw.b2[side];
    int i = blockIdx.x * blockDim.x + threadIdx.x;
    if (i >= (cfg::BT / 4) * (cfg::C / 8)) return;
    const int c8 = (i & (cfg::C / 8 - 1)) * 8;
    const int tq = i >> 6;
    const int b  = tq >> 9;
    const int t0 = (tq & 511) * 4;
    const size_t rbase = ((size_t)b * cfg::T + t0) * cfg::C + c8;

    BF8 r[6];
#pragma unroll
    for (int j = 0; j < 6; j++) {
        int t = t0 - 1 + j;
        if (t >= 0 && t < cfg::T)
            r[j].u = *reinterpret_cast<const uint4*>(h + rbase + (size_t)(j - 1) * cfg::C);
        else
            r[j].u = make_uint4(0, 0, 0, 0);
    }

    float4 wv[6];
#pragma unroll
    for (int k = 0; k < 6; k++) wv[k] = reinterpret_cast<const float4*>(w2 + c8 * 3)[k];
    const float* wf = reinterpret_cast<const float*>(wv);
    float4 bv0 = *reinterpret_cast<const float4*>(b2 + c8);
    float4 bv1 = *reinterpret_cast<const float4*>(b2 + c8 + 4);
    float bb[8] = {bv0.x, bv0.y, bv0.z, bv0.w, bv1.x, bv1.y, bv1.z, bv1.w};

#pragma unroll
    for (int k = 0; k < 4; k++) {
        BF8 o;
#pragma unroll
        for (int p = 0; p < 4; p++) {
            float2 pp = __bfloat1622float2(r[k].h2[p]);
            float2 cc = __bfloat1622float2(r[k + 1].h2[p]);
            float2 nn = __bfloat1622float2(r[k + 2].h2[p]);
            int j0 = 2 * p, j1 = 2 * p + 1;
            float v0 = pp.x * wf[j0 * 3 + 0] + cc.x * wf[j0 * 3 + 1] + nn.x * wf[j0 * 3 + 2] + bb[j0];
            float v1 = pp.y * wf[j1 * 3 + 0] + cc.y * wf[j1 * 3 + 1] + nn.y * wf[j1 * 3 + 2] + bb[j1];
            o.h2[p] = __floats2bfloat162_rn(v0, v1);
        }
        *reinterpret_cast<uint4*>(out + rbase + (size_t)k * cfg::C) = o.u;
    }
}

// depthwise conv k=3 + transpose: h[2+side] (B,T,C) -> g_VT[1-side] (B,C,T)
__global__ void k_dwconv_t(const __nv_bfloat16* __restrict__ hbase,
                           __nv_bfloat16* __restrict__ vtbase, DW2 dw) {
    __shared__ __nv_bfloat16 s[66][40];
    const int z = blockIdx.z;
    const int side = z >> 3, b = z & 7;
    const int t0 = blockIdx.x * 64, c0 = blockIdx.y * 32;
    const __nv_bfloat16* hb = hbase + (size_t)(2 + side) * cfg::BT * cfg::C
                                    + (size_t)b * cfg::T * cfg::C;
    __nv_bfloat16* outT = vtbase + (size_t)(1 - side) * cfg::B * cfg::C * cfg::T
                                 + (size_t)b * cfg::C * cfg::T;
    const int tid = threadIdx.x;
    for (int slot = tid; slot < 66 * 4; slot += 256) {
        int row = slot >> 2, q = slot & 3;
        int t = t0 + row - 1;
        uint4 val = make_uint4(0, 0, 0, 0);
        if (t >= 0 && t < cfg::T)
            val = *reinterpret_cast<const uint4*>(hb + (size_t)t * cfg::C + c0 + q * 8);
        *reinterpret_cast<uint4*>(&s[row][q * 8]) = val;
    }
    __syncthreads();

    const int c = tid >> 3;
    const int g = tid & 7;
    const int cg = c0 + c;
    const float w0 = dw.w2[side][cg * 3 + 0];
    const float w1 = dw.w2[side][cg * 3 + 1];
    const float w2v = dw.w2[side][cg * 3 + 2];
    const float bb = dw.b2[side][cg];

    BF8 o;
#pragma unroll
    for (int p = 0; p < 4; p++) {
        int tt0 = g * 8 + 2 * p, tt1 = tt0 + 1;
        float v0 = __bfloat162float(s[tt0][c]) * w0 + __bfloat162float(s[tt0 + 1][c]) * w1
                 + __bfloat162float(s[tt0 + 2][c]) * w2v + bb;
        float v1 = __bfloat162float(s[tt1][c]) * w0 + __bfloat162float(s[tt1 + 1][c]) * w1
                 + __bfloat162float(s[tt1 + 2][c]) * w2v + bb;
        o.h2[p] = __floats2bfloat162_rn(v0, v1);
    }
    *reinterpret_cast<uint4*>(outT + (size_t)cg * cfg::T + t0 + g * 8) = o.u;
}

// row softmax: uint4 load/store, shfl reductions
__global__ void k_softmax(const __nv_bfloat16* __restrict__ Sp,
                          const __nv_bfloat16* __restrict__ S2,
                          __nv_bfloat16* __restrict__ Pb) {
    const size_t row = blockIdx.x;
    const int y = blockIdx.y;
    const __nv_bfloat16* s = (y == 0 ? Sp : S2) + row * cfg::T;
    __nv_bfloat16* p = Pb + (size_t)y * cfg::B * cfg::T * cfg::T + row * cfg::T;
    const int tid = threadIdx.x;
    const int lane = tid & 31, wid = tid >> 5;

    BF8 in;
    in.u = *reinterpret_cast<const uint4*>(s + tid * 8);
    float v[8];
#pragma unroll
    for (int pq = 0; pq < 4; pq++) {
        float2 f = __bfloat1622float2(in.h2[pq]);
        v[2 * pq] = f.x; v[2 * pq + 1] = f.y;
    }

    float m = v[0];
#pragma unroll
    for (int j = 1; j < 8; j++) m = fmaxf(m, v[j]);
#pragma unroll
    for (int o = 16; o > 0; o >>= 1) m = fmaxf(m, __shfl_xor_sync(0xFFFFFFFFu, m, o));
    __shared__ float sm[8], ss[8];
    if (lane == 0) sm[wid] = m;
    __syncthreads();
    m = sm[0];
#pragma unroll
    for (int j = 1; j < 8; j++) m = fmaxf(m, sm[j]);

    float sum = 0.f;
#pragma unroll
    for (int j = 0; j < 8; j++) { v[j] = __expf(v[j] - m); sum += v[j]; }
#pragma unroll
    for (int o = 16; o > 0; o >>= 1) sum += __shfl_xor_sync(0xFFFFFFFFu, sum, o);
    if (lane == 0) ss[wid] = sum;
    __syncthreads();
    float tot = ss[0];
#pragma unroll
    for (int j = 1; j < 8; j++) tot += ss[j];
    const float inv = 1.f / tot;

    BF8 o;
#pragma unroll
    for (int pq = 0; pq < 4; pq++)
        o.h2[pq] = __floats2bfloat162_rn(v[2 * pq] * inv, v[2 * pq + 1] * inv);
    *reinterpret_cast<uint4*>(p + tid * 8) = o.u;
}

// ---------------- host ----------------
template <typename Tp>
static Tp* sym(const void* s) {
    void* p = nullptr;
    cudaGetSymbolAddress(&p, s);
    return reinterpret_cast<Tp*>(p);
}

extern "C" void kernel_launch(void* const* d_in, const int* in_sizes, int n_in,
                              void* d_out, int out_size) {
    using namespace cfg;
    const float* x_l    = (const float*)d_in[0];
    const float* x_r    = (const float*)d_in[1];
    const float* lp1_w1 = (const float*)d_in[2];  const float* lp1_b1 = (const float*)d_in[3];
    const float* lp1_w2 = (const float*)d_in[4];  const float* lp1_b2 = (const float*)d_in[5];
    const float* rp1_w1 = (const float*)d_in[6];  const float* rp1_b1 = (const float*)d_in[7];
    const float* rp1_w2 = (const float*)d_in[8];  const float* rp1_b2 = (const float*)d_in[9];
    const float* lp2_w1 = (const float*)d_in[10]; const float* lp2_b1 = (const float*)d_in[11];
    const float* lp2_w2 = (const float*)d_in[12]; const float* lp2_b2 = (const float*)d_in[13];
    const float* rp2_w1 = (const float*)d_in[14]; const float* rp2_b1 = (const float*)d_in[15];
    const float* rp2_w2 = (const float*)d_in[16]; const float* rp2_b2 = (const float*)d_in[17];
    const float* lp3_w  = (const float*)d_in[18]; const float* lp3_b  = (const float*)d_in[19];
    const float* rp3_w  = (const float*)d_in[20]; const float* rp3_b  = (const float*)d_in[21];

    __nv_bfloat16* X   = sym<__nv_bfloat16>(g_X);
    __nv_bfloat16* w16 = sym<__nv_bfloat16>(g_w16);
    __nv_bfloat16* h   = sym<__nv_bfloat16>(g_h);
    __nv_bfloat16* Q   = sym<__nv_bfloat16>(g_Q);
    __nv_bfloat16* VT  = sym<__nv_bfloat16>(g_VT);
    __nv_bfloat16* Sp  = sym<__nv_bfloat16>(g_S);
    __nv_bfloat16* S2  = sym<__nv_bfloat16>(g_S2);
    __nv_bfloat16* P   = sym<__nv_bfloat16>(g_P);
    __nv_bfloat16* F   = sym<__nv_bfloat16>(g_F);

    const int n  = BT * C;
    const int nw = C * C;
    const float scale = 0.04419417382415922f;  // 512^-0.5
    const int DSM = 3 * (128 + 64) * 128;      // 73728 B

    cudaFuncSetAttribute(k_gemmB<0>, cudaFuncAttributeMaxDynamicSharedMemorySize, DSM);
    cudaFuncSetAttribute(k_gemmB<1>, cudaFuncAttributeMaxDynamicSharedMemorySize, DSM);
    cudaFuncSetAttribute(k_gemmB<2>, cudaFuncAttributeMaxDynamicSharedMemorySize, DSM);

    P4 nob = {{nullptr, nullptr, nullptr, nullptr}};

    k_f2bf_x<<<(2 * (n / 4) + 255) / 256, 256>>>(x_l, x_r, X, n / 4);
    k_f2bf6<<<(6 * (nw / 4)) / 256, 256>>>(lp1_w1, rp1_w1, lp2_w1, rp2_w1, lp3_w, rp3_w, w16);

    // 4 projection GEMMs, one launch
    {
        P4 pb = {{lp1_b1, rp1_b1, lp2_b1, rp2_b1}};
        dim3 g(C / 64, BT / 128, 4);
        k_gemmB<0><<<g, 256, DSM>>>(X, w16, h, nullptr, pb, nob,
                                    C, C, C, C, (long long)n, (long long)nw, (long long)n,
                                    1, 1.f);
    }

    // dwconv Q + dwconv-transpose V
    {
        DW2 dq = {{lp1_w2, rp1_w2}, {lp1_b2, rp1_b2}};
        k_dwconv<<<dim3(((BT / 4) * (C / 8) + 255) / 256, 2), 256>>>(h, Q, dq);
        DW2 dv = {{lp2_w2, rp2_w2}, {lp2_b2, rp2_b2}};
        k_dwconv_t<<<dim3(T / 64, C / 32, 16), 256>>>(h, VT, dv);
    }

    // S = scale * Ql.Qr with dual store (S + S^T)
    {
        dim3 g(T / 64, T / 128, B);
        k_gemmB<2><<<g, 256, DSM>>>(Q, Q + n, Sp, S2, nob, nob,
                                    C, C, C, T,
                                    (long long)T * C, (long long)T * C, (long long)T * T,
                                    -1, scale);
    }

    // both softmaxes in one launch
    k_softmax<<<dim3(B * T, 2), 256>>>(Sp, S2, P);

    // F GEMMs
    {
        dim3 g(C / 64, T / 128, 16);
        k_gemmB<0><<<g, 256, DSM>>>(P, VT, F, nullptr, nob, nob,
                                    T, T, T, C,
                                    (long long)T * T, (long long)C * T, (long long)T * C,
                                    -1, 1.f);
    }

    // out GEMMs with residual
    {
        P4 ob = {{lp3_b, rp3_b, nullptr, nullptr}};
        P4 orr = {{x_l, x_r, nullptr, nullptr}};
        dim3 g(C / 64, BT / 128, 2);
        k_gemmB<1><<<g, 256, DSM>>>(F, w16 + 4 * nw, d_out, nullptr, ob, orr,
                                    C, C, C, C,
                                    (long long)n, (long long)nw, (long long)n,
                                    -1, 1.f);
    }
}

// round 13
// speedup vs baseline: 1.0746x; 1.0746x over previous
#include <cuda_runtime.h>
#include <cuda_bf16.h>
#include <cstdint>

namespace cfg {
constexpr int B = 8, T = 2048, C = 512;
constexpr int BT = B * T;  // 16384
}

// ---------------- scratch (static device arrays; no allocation) ----------------
__device__ __align__(128) __nv_bfloat16 g_X[2 * cfg::BT * cfg::C];       // [xl, xr]
__device__ __align__(128) __nv_bfloat16 g_w16[6 * cfg::C * cfg::C];      // lp1,rp1,lp2,rp2,lp3,rp3
__device__ __align__(128) __nv_bfloat16 g_h[4 * cfg::BT * cfg::C];       // proj outputs
__device__ __align__(128) __nv_bfloat16 g_Q[2 * cfg::BT * cfg::C];       // [Ql, Qr]
__device__ __align__(128) __nv_bfloat16 g_VT[2 * cfg::B * cfg::C * cfg::T]; // [VrT, VlT]
__device__ __align__(128) __nv_bfloat16 g_S [(size_t)cfg::B * cfg::T * cfg::T];
__device__ __align__(128) __nv_bfloat16 g_S2[(size_t)cfg::B * cfg::T * cfg::T];
__device__ __align__(128) __nv_bfloat16 g_P [2 * (size_t)cfg::B * cfg::T * cfg::T]; // [P1, P2]
__device__ __align__(128) __nv_bfloat16 g_F [2 * cfg::BT * cfg::C];      // [F1, F2]

struct P4 { const float* p[4]; };
struct DW2 { const float* w2[2]; const float* b2[2]; };

// ---------------- helpers ----------------
__device__ __forceinline__ uint32_t smem_u32(const void* p) {
    uint32_t a;
    asm("{ .reg .u64 t; cvta.to.shared.u64 t, %1; cvt.u32.u64 %0, t; }" : "=r"(a) : "l"(p));
    return a;
}

#define CP_ASYNC16(dst, src) \
    asm volatile("cp.async.cg.shared.global [%0], [%1], 16;" :: "r"(dst), "l"(src) : "memory")
#define CP_COMMIT() asm volatile("cp.async.commit_group;" ::: "memory")
#define CP_WAIT(n)  asm volatile("cp.async.wait_group %0;" :: "n"(n) : "memory")

#define LDSM4(r, addr) \
    asm volatile("ldmatrix.sync.aligned.m8n8.x4.shared.b16 {%0,%1,%2,%3}, [%4];" \
        : "=r"((r)[0]), "=r"((r)[1]), "=r"((r)[2]), "=r"((r)[3]) : "r"(addr))

#define MMA16816(c, a, b0, b1) \
    asm volatile("mma.sync.aligned.m16n8k16.row.col.f32.bf16.bf16.f32 " \
        "{%0,%1,%2,%3}, {%4,%5,%6,%7}, {%8,%9}, {%0,%1,%2,%3};" \
        : "+f"((c)[0]), "+f"((c)[1]), "+f"((c)[2]), "+f"((c)[3]) \
        : "r"((a)[0]), "r"((a)[1]), "r"((a)[2]), "r"((a)[3]), "r"(b0), "r"(b1))

#define SW128(o) ((o) ^ (((o) >> 3) & 0x70))

union BF8 { uint4 u; __nv_bfloat162 h2[4]; };

// ---------------- bf16 mma.sync GEMM (R10-proven: BM=BN=128, BK=64, NS=3, 2 CTAs) ----------------
template <int MODE>
__global__ __launch_bounds__(256, 2)
void k_gemmB(const __nv_bfloat16* __restrict__ A,
             const __nv_bfloat16* __restrict__ Bm,
             void* __restrict__ Cout, void* __restrict__ C2,
             P4 bias, P4 res,
             int K, int lda, int ldb, int ldc,
             long long sA, long long sB, long long sC,
             int zAmask, float scale) {
    constexpr int NS = 3;
    constexpr int STAGE = 2 * 128 * 128;
    extern __shared__ __align__(16) char dyn_raw[];
    const uint32_t sbase = smem_u32(dyn_raw);

    const int tid = threadIdx.x;
    const int lane = tid & 31, w = tid >> 5;
    const int wm = w & 3, wn = w >> 2;
    const int m0 = blockIdx.y * 128;
    const int n0 = blockIdx.x * 128;
    const int bz = blockIdx.z;
    A  += (size_t)(bz & zAmask) * sA;
    Bm += (size_t)bz * sB;

    const int nk = K >> 6;

    auto issue = [&](int kc, int s) {
        const uint32_t aB = sbase + s * STAGE;
        const uint32_t bB = aB + 16384;
        const __nv_bfloat16* Ag = A + (size_t)kc * 64;
        const __nv_bfloat16* Bg = Bm + (size_t)kc * 64;
#pragma unroll
        for (int i = 0; i < 4; i++) {
            int slot = tid + i * 256;
            int row = slot >> 3, v = slot & 7;
            CP_ASYNC16(aB + SW128(row * 128 + v * 16),
                       (const void*)(Ag + (size_t)(m0 + row) * lda + v * 8));
        }
#pragma unroll
        for (int i = 0; i < 4; i++) {
            int slot = tid + i * 256;
            int row = slot >> 3, v = slot & 7;
            CP_ASYNC16(bB + SW128(row * 128 + v * 16),
                       (const void*)(Bg + (size_t)(n0 + row) * ldb + v * 8));
        }
    };

    const uint32_t sxor = (uint32_t)(lane & 7) << 4;
    const uint32_t a_row = wm * 32 + (lane & 15);
    const uint32_t a_bc0 = (uint32_t)(lane >> 4) * 16;
    const uint32_t b_row = wn * 64 + (lane & 7) + ((lane >> 4) << 3);
    const uint32_t b_bc0 = (uint32_t)((lane >> 3) & 1) * 16;

    float acc[2][8][4];
#pragma unroll
    for (int mi = 0; mi < 2; mi++)
#pragma unroll
        for (int nj = 0; nj < 8; nj++)
#pragma unroll
            for (int e = 0; e < 4; e++) acc[mi][nj][e] = 0.f;

#pragma unroll
    for (int p = 0; p < NS - 1; p++) { issue(p, p); CP_COMMIT(); }
    CP_WAIT(NS - 2);
    __syncthreads();

    for (int kb = 0; kb < nk; kb++) {
        if (kb + NS - 1 < nk) issue(kb + NS - 1, (kb + NS - 1) % NS);
        CP_COMMIT();

        const uint32_t aB = sbase + (kb % NS) * STAGE;
        const uint32_t bB = aB + 16384;
#pragma unroll
        for (int ks = 0; ks < 4; ks++) {
            uint32_t af[2][4], bf[4][4];
            const uint32_t abc = ((uint32_t)ks * 32 + a_bc0) ^ sxor;
            const uint32_t bbc = ((uint32_t)ks * 32 + b_bc0) ^ sxor;
#pragma unroll
            for (int mi = 0; mi < 2; mi++)
                LDSM4(af[mi], aB + (a_row + mi * 16) * 128 + abc);
#pragma unroll
            for (int nb = 0; nb < 4; nb++)
                LDSM4(bf[nb], bB + (b_row + nb * 16) * 128 + bbc);
#pragma unroll
            for (int mi = 0; mi < 2; mi++)
#pragma unroll
                for (int nj = 0; nj < 8; nj++)
                    MMA16816(acc[mi][nj], af[mi], bf[nj >> 1][(nj & 1) * 2], bf[nj >> 1][(nj & 1) * 2 + 1]);
        }
        CP_WAIT(NS - 2);
        __syncthreads();
    }

    const size_t cb = (size_t)bz * sC;

    if constexpr (MODE == 2) { CP_WAIT(0); __syncthreads(); }
    unsigned short* sst = reinterpret_cast<unsigned short*>(dyn_raw);

    const float* bp = bias.p[bz & 3];
    const float* rp = res.p[bz & 3];

#pragma unroll
    for (int mi = 0; mi < 2; mi++) {
        const int r0 = m0 + wm * 32 + mi * 16 + (lane >> 2);
        const int rl = wm * 32 + mi * 16 + (lane >> 2);
#pragma unroll
        for (int nj = 0; nj < 8; nj++) {
            const int c = n0 + wn * 64 + nj * 8 + (lane & 3) * 2;
            const int cl = wn * 64 + nj * 8 + (lane & 3) * 2;
            float v0 = acc[mi][nj][0] * scale, v1 = acc[mi][nj][1] * scale;
            float v2 = acc[mi][nj][2] * scale, v3 = acc[mi][nj][3] * scale;
            if constexpr (MODE == 0) {
                if (bp) {
                    float b0 = bp[c], b1 = bp[c + 1];
                    v0 += b0; v1 += b1; v2 += b0; v3 += b1;
                }
                __nv_bfloat16* O = (__nv_bfloat16*)Cout;
                *reinterpret_cast<__nv_bfloat162*>(&O[cb + (size_t)r0 * ldc + c]) =
                    __floats2bfloat162_rn(v0, v1);
                *reinterpret_cast<__nv_bfloat162*>(&O[cb + (size_t)(r0 + 8) * ldc + c]) =
                    __floats2bfloat162_rn(v2, v3);
            } else if constexpr (MODE == 1) {
                float b0 = bp[c], b1 = bp[c + 1];
                float* O = (float*)Cout;
                size_t o1 = cb + (size_t)r0 * ldc + c;
                size_t o2 = cb + (size_t)(r0 + 8) * ldc + c;
                float2 r1 = *reinterpret_cast<const float2*>(&rp[(size_t)r0 * ldc + c]);
                float2 r2 = *reinterpret_cast<const float2*>(&rp[(size_t)(r0 + 8) * ldc + c]);
                *reinterpret_cast<float2*>(&O[o1]) = make_float2(v0 + b0 + r1.x, v1 + b1 + r1.y);
                *reinterpret_cast<float2*>(&O[o2]) = make_float2(v2 + b0 + r2.x, v3 + b1 + r2.y);
            } else {  // MODE 2
                __nv_bfloat16* O = (__nv_bfloat16*)Cout;
                __nv_bfloat162 p1 = __floats2bfloat162_rn(v0, v1);
                __nv_bfloat162 p2 = __floats2bfloat162_rn(v2, v3);
                *reinterpret_cast<__nv_bfloat162*>(&O[cb + (size_t)r0 * ldc + c]) = p1;
                *reinterpret_cast<__nv_bfloat162*>(&O[cb + (size_t)(r0 + 8) * ldc + c]) = p2;
                *reinterpret_cast<__nv_bfloat162*>(&sst[rl * 136 + cl]) = p1;
                *reinterpret_cast<__nv_bfloat162*>(&sst[(rl + 8) * 136 + cl]) = p2;
            }
        }
    }

    if constexpr (MODE == 2) {
        __syncthreads();
        __nv_bfloat16* O2 = (__nv_bfloat16*)C2;
#pragma unroll
        for (int it = 0; it < 8; it++) {
            const int nn = it * 16 + (tid >> 4);
            const int mm = (tid & 15) * 8;
            unsigned short u[8];
#pragma unroll
            for (int j = 0; j < 8; j++) u[j] = sst[(mm + j) * 136 + nn];
            uint4 o;
            o.x = u[0] | ((uint32_t)u[1] << 16);
            o.y = u[2] | ((uint32_t)u[3] << 16);
            o.z = u[4] | ((uint32_t)u[5] << 16);
            o.w = u[6] | ((uint32_t)u[7] << 16);
            *reinterpret_cast<uint4*>(&O2[cb + (size_t)(n0 + nn) * ldc + m0 + mm]) = o;
        }
    }
}

// ---------------- fused conversion: x_l, x_r, 6 weights in one launch ----------------
// blocks [0, NXB) -> x conversion; blocks [NXB, NXB+NWB) -> weight conversion
__global__ void k_convert(const float* __restrict__ xl, const float* __restrict__ xr,
                          __nv_bfloat16* __restrict__ outX,
                          const float* s0, const float* s1, const float* s2,
                          const float* s3, const float* s4, const float* s5,
                          __nv_bfloat16* __restrict__ outW,
                          int n4, int nxb) {
    if ((int)blockIdx.x < nxb) {
        int i = blockIdx.x * blockDim.x + threadIdx.x;
        if (i < 2 * n4) {
            const float* s = (i < n4) ? xl : xr;
            int off = (i < n4) ? i : i - n4;
            float4 f = reinterpret_cast<const float4*>(s)[off];
            __nv_bfloat162* o = reinterpret_cast<__nv_bfloat162*>(outX) + 2 * (size_t)i;
            o[0] = __floats2bfloat162_rn(f.x, f.y);
            o[1] = __floats2bfloat162_rn(f.z, f.w);
        }
    } else {
        int i = (blockIdx.x - nxb) * blockDim.x + threadIdx.x;  // < 6*65536
        int which = i >> 16, off = i & 65535;
        const float* s = which == 0 ? s0 : which == 1 ? s1 : which == 2 ? s2
                        : which == 3 ? s3 : which == 4 ? s4 : s5;
        float4 f = reinterpret_cast<const float4*>(s)[off];
        __nv_bfloat162* o = reinterpret_cast<__nv_bfloat162*>(outW + ((size_t)which << 18));
        o[2 * off]     = __floats2bfloat162_rn(f.x, f.y);
        o[2 * off + 1] = __floats2bfloat162_rn(f.z, f.w);
    }
}

// ---------------- fused depthwise conv: Q path + V-transpose path in one launch ----------------
// blocks [0, 4096): dwconv (side = bid>>11, i = (bid&2047)*256+tid)
// blocks [4096, 12288): dwconv_t (t = bid-4096; z = t>>9; r = t&511; bx = r&31; by = r>>5)
struct DW4 { const float* w2[4]; const float* b2[4]; };  // [q_l, q_r, v_l, v_r]

__global__ void k_dwconv_all(const __nv_bfloat16* __restrict__ hbase,
                             __nv_bfloat16* __restrict__ qbase,
                             __nv_bfloat16* __restrict__ vtbase, DW4 dw) {
    __shared__ __nv_bfloat16 s[66][40];
    const int bid = blockIdx.x;
    const int tid = threadIdx.x;

    if (bid < 4096) {
        // ---- Q path: 8 channels x 4 t-positions per thread ----
        const int side = bid >> 11;
        const __nv_bfloat16* h = hbase + (size_t)side * cfg::BT * cfg::C;
        __nv_bfloat16* out = qbase + (size_t)side * cfg::BT * cfg::C;
        const float* w2 = dw.w2[side];
        const float* b2 = dw.b2[side];
        int i = (bid & 2047) * 256 + tid;
        if (i >= (cfg::BT / 4) * (cfg::C / 8)) return;
        const int c8 = (i & (cfg::C / 8 - 1)) * 8;
        const int tq = i >> 6;
        const int b  = tq >> 9;
        const int t0 = (tq & 511) * 4;
        const size_t rbase = ((size_t)b * cfg::T + t0) * cfg::C + c8;

        BF8 r[6];
#pragma unroll
        for (int j = 0; j < 6; j++) {
            int t = t0 - 1 + j;
            if (t >= 0 && t < cfg::T)
                r[j].u = *reinterpret_cast<const uint4*>(h + rbase + (size_t)(j - 1) * cfg::C);
            else
                r[j].u = make_uint4(0, 0, 0, 0);
        }

        float4 wv[6];
#pragma unroll
        for (int k = 0; k < 6; k++) wv[k] = reinterpret_cast<const float4*>(w2 + c8 * 3)[k];
        const float* wf = reinterpret_cast<const float*>(wv);
        float4 bv0 = *reinterpret_cast<const float4*>(b2 + c8);
        float4 bv1 = *reinterpret_cast<const float4*>(b2 + c8 + 4);
        float bb[8] = {bv0.x, bv0.y, bv0.z, bv0.w, bv1.x, bv1.y, bv1.z, bv1.w};

#pragma unroll
        for (int k = 0; k < 4; k++) {
            BF8 o;
#pragma unroll
            for (int p = 0; p < 4; p++) {
                float2 pp = __bfloat1622float2(r[k].h2[p]);
                float2 cc = __bfloat1622float2(r[k + 1].h2[p]);
                float2 nn = __bfloat1622float2(r[k + 2].h2[p]);
                int j0 = 2 * p, j1 = 2 * p + 1;
                float v0 = pp.x * wf[j0 * 3 + 0] + cc.x * wf[j0 * 3 + 1] + nn.x * wf[j0 * 3 + 2] + bb[j0];
                float v1 = pp.y * wf[j1 * 3 + 0] + cc.y * wf[j1 * 3 + 1] + nn.y * wf[j1 * 3 + 2] + bb[j1];
                o.h2[p] = __floats2bfloat162_rn(v0, v1);
            }
            *reinterpret_cast<uint4*>(out + rbase + (size_t)k * cfg::C) = o.u;
        }
    } else {
        // ---- V path: dwconv + transpose (64 t x 32 c tile) ----
        const int t4 = bid - 4096;
        const int z = t4 >> 9;
        const int rblk = t4 & 511;
        const int t0 = (rblk & 31) * 64;
        const int c0 = (rblk >> 5) * 32;
        const int side = z >> 3, b = z & 7;
        const __nv_bfloat16* hb = hbase + (size_t)(2 + side) * cfg::BT * cfg::C
                                        + (size_t)b * cfg::T * cfg::C;
        __nv_bfloat16* outT = vtbase + (size_t)(1 - side) * cfg::B * cfg::C * cfg::T
                                     + (size_t)b * cfg::C * cfg::T;
        const float* w2 = dw.w2[2 + side];
        const float* b2 = dw.b2[2 + side];
        for (int slot = tid; slot < 66 * 4; slot += 256) {
            int row = slot >> 2, q = slot & 3;
            int t = t0 + row - 1;
            uint4 val = make_uint4(0, 0, 0, 0);
            if (t >= 0 && t < cfg::T)
                val = *reinterpret_cast<const uint4*>(hb + (size_t)t * cfg::C + c0 + q * 8);
            *reinterpret_cast<uint4*>(&s[row][q * 8]) = val;
        }
        __syncthreads();

        const int c = tid >> 3;
        const int g = tid & 7;
        const int cg = c0 + c;
        const float w0 = w2[cg * 3 + 0];
        const float w1 = w2[cg * 3 + 1];
        const float w2v = w2[cg * 3 + 2];
        const float bb = b2[cg];

        BF8 o;
#pragma unroll
        for (int p = 0; p < 4; p++) {
            int tt0 = g * 8 + 2 * p, tt1 = tt0 + 1;
            float v0 = __bfloat162float(s[tt0][c]) * w0 + __bfloat162float(s[tt0 + 1][c]) * w1
                     + __bfloat162float(s[tt0 + 2][c]) * w2v + bb;
            float v1 = __bfloat162float(s[tt1][c]) * w0 + __bfloat162float(s[tt1 + 1][c]) * w1
                     + __bfloat162float(s[tt1 + 2][c]) * w2v + bb;
            o.h2[p] = __floats2bfloat162_rn(v0, v1);
        }
        *reinterpret_cast<uint4*>(outT + (size_t)cg * cfg::T + t0 + g * 8) = o.u;
    }
}

// ---------------- row softmax: uint4 load/store, shfl reductions ----------------
__global__ void k_softmax(const __nv_bfloat16* __restrict__ Sp,
                          const __nv_bfloat16* __restrict__ S2,
                          __nv_bfloat16* __restrict__ Pb) {
    const size_t row = blockIdx.x;
    const int y = blockIdx.y;
    const __nv_bfloat16* s = (y == 0 ? Sp : S2) + row * cfg::T;
    __nv_bfloat16* p = Pb + (size_t)y * cfg::B * cfg::T * cfg::T + row * cfg::T;
    const int tid = threadIdx.x;
    const int lane = tid & 31, wid = tid >> 5;

    BF8 in;
    in.u = *reinterpret_cast<const uint4*>(s + tid * 8);
    float v[8];
#pragma unroll
    for (int pq = 0; pq < 4; pq++) {
        float2 f = __bfloat1622float2(in.h2[pq]);
        v[2 * pq] = f.x; v[2 * pq + 1] = f.y;
    }

    float m = v[0];
#pragma unroll
    for (int j = 1; j < 8; j++) m = fmaxf(m, v[j]);
#pragma unroll
    for (int o = 16; o > 0; o >>= 1) m = fmaxf(m, __shfl_xor_sync(0xFFFFFFFFu, m, o));
    __shared__ float sm[8], ss[8];
    if (lane == 0) sm[wid] = m;
    __syncthreads();
    m = sm[0];
#pragma unroll
    for (int j = 1; j < 8; j++) m = fmaxf(m, sm[j]);

    float sum = 0.f;
#pragma unroll
    for (int j = 0; j < 8; j++) { v[j] = __expf(v[j] - m); sum += v[j]; }
#pragma unroll
    for (int o = 16; o > 0; o >>= 1) sum += __shfl_xor_sync(0xFFFFFFFFu, sum, o);
    if (lane == 0) ss[wid] = sum;
    __syncthreads();
    float tot = ss[0];
#pragma unroll
    for (int j = 1; j < 8; j++) tot += ss[j];
    const float inv = 1.f / tot;

    BF8 o;
#pragma unroll
    for (int pq = 0; pq < 4; pq++)
        o.h2[pq] = __floats2bfloat162_rn(v[2 * pq] * inv, v[2 * pq + 1] * inv);
    *reinterpret_cast<uint4*>(p + tid * 8) = o.u;
}

// ---------------- host ----------------
template <typename Tp>
static Tp* sym(const void* s) {
    void* p = nullptr;
    cudaGetSymbolAddress(&p, s);
    return reinterpret_cast<Tp*>(p);
}

extern "C" void kernel_launch(void* const* d_in, const int* in_sizes, int n_in,
                              void* d_out, int out_size) {
    using namespace cfg;
    const float* x_l    = (const float*)d_in[0];
    const float* x_r    = (const float*)d_in[1];
    const float* lp1_w1 = (const float*)d_in[2];  const float* lp1_b1 = (const float*)d_in[3];
    const float* lp1_w2 = (const float*)d_in[4];  const float* lp1_b2 = (const float*)d_in[5];
    const float* rp1_w1 = (const float*)d_in[6];  const float* rp1_b1 = (const float*)d_in[7];
    const float* rp1_w2 = (const float*)d_in[8];  const float* rp1_b2 = (const float*)d_in[9];
    const float* lp2_w1 = (const float*)d_in[10]; const float* lp2_b1 = (const float*)d_in[11];
    const float* lp2_w2 = (const float*)d_in[12]; const float* lp2_b2 = (const float*)d_in[13];
    const float* rp2_w1 = (const float*)d_in[14]; const float* rp2_b1 = (const float*)d_in[15];
    const float* rp2_w2 = (const float*)d_in[16]; const float* rp2_b2 = (const float*)d_in[17];
    const float* lp3_w  = (const float*)d_in[18]; const float* lp3_b  = (const float*)d_in[19];
    const float* rp3_w  = (const float*)d_in[20]; const float* rp3_b  = (const float*)d_in[21];

    __nv_bfloat16* X   = sym<__nv_bfloat16>(g_X);
    __nv_bfloat16* w16 = sym<__nv_bfloat16>(g_w16);
    __nv_bfloat16* h   = sym<__nv_bfloat16>(g_h);
    __nv_bfloat16* Q   = sym<__nv_bfloat16>(g_Q);
    __nv_bfloat16* VT  = sym<__nv_bfloat16>(g_VT);
    __nv_bfloat16* Sp  = sym<__nv_bfloat16>(g_S);
    __nv_bfloat16* S2  = sym<__nv_bfloat16>(g_S2);
    __nv_bfloat16* P   = sym<__nv_bfloat16>(g_P);
    __nv_bfloat16* F   = sym<__nv_bfloat16>(g_F);

    const int n  = BT * C;
    const int nw = C * C;
    const float scale = 0.04419417382415922f;  // 512^-0.5
    const int DSM = 3 * 2 * 128 * 128;         // 98304 B

    cudaFuncSetAttribute(k_gemmB<0>, cudaFuncAttributeMaxDynamicSharedMemorySize, DSM);
    cudaFuncSetAttribute(k_gemmB<1>, cudaFuncAttributeMaxDynamicSharedMemorySize, DSM);
    cudaFuncSetAttribute(k_gemmB<2>, cudaFuncAttributeMaxDynamicSharedMemorySize, DSM);

    P4 nob = {{nullptr, nullptr, nullptr, nullptr}};

    // fused conversions: x (16384 blocks) + weights (1536 blocks)
    {
        const int nxb = (2 * (n / 4) + 255) / 256;  // 16384
        const int nwb = (6 * (nw / 4)) / 256;       // 1536
        k_convert<<<nxb + nwb, 256>>>(x_l, x_r, X,
                                      lp1_w1, rp1_w1, lp2_w1, rp2_w1, lp3_w, rp3_w,
                                      w16, n / 4, nxb);
    }

    // 4 projection GEMMs, one launch
    {
        P4 pb = {{lp1_b1, rp1_b1, lp2_b1, rp2_b1}};
        dim3 g(C / 128, BT / 128, 4);
        k_gemmB<0><<<g, 256, DSM>>>(X, w16, h, nullptr, pb, nob,
                                    C, C, C, C, (long long)n, (long long)nw, (long long)n,
                                    1, 1.f);
    }

    // fused dwconv: Q path (4096 blocks) + V-transpose path (8192 blocks)
    {
        DW4 dw = {{lp1_w2, rp1_w2, lp2_w2, rp2_w2}, {lp1_b2, rp1_b2, lp2_b2, rp2_b2}};
        k_dwconv_all<<<12288, 256>>>(h, Q, VT, dw);
    }

    // S = scale * Ql.Qr with dual store (S + S^T)
    {
        dim3 g(T / 128, T / 128, B);
        k_gemmB<2><<<g, 256, DSM>>>(Q, Q + n, Sp, S2, nob, nob,
                                    C, C, C, T,
                                    (long long)T * C, (long long)T * C, (long long)T * T,
                                    -1, scale);
    }

    // both softmaxes in one launch
    k_softmax<<<dim3(B * T, 2), 256>>>(Sp, S2, P);

    // F GEMMs
    {
        dim3 g(C / 128, T / 128, 16);
        k_gemmB<0><<<g, 256, DSM>>>(P, VT, F, nullptr, nob, nob,
                                    T, T, T, C,
                                    (long long)T * T, (long long)C * T, (long long)T * C,
                                    -1, 1.f);
    }

    // out GEMMs with residual
    {
        P4 ob = {{lp3_b, rp3_b, nullptr, nullptr}};
        P4 orr = {{x_l, x_r, nullptr, nullptr}};
        dim3 g(C / 128, BT / 128, 2);
        k_gemmB<1><<<g, 256, DSM>>>(F, w16 + 4 * nw, d_out, nullptr, ob, orr,
                                    C, C, C, C,
                                    (long long)n, (long long)nw, (long long)n,
                                    -1, 1.f);
    }
}

// round 16
// speedup vs baseline: 1.1932x; 1.1104x over previous
#include <cuda_runtime.h>
#include <cuda_bf16.h>
#include <cstdint>

namespace cfg {
constexpr int B = 8, T = 2048, C = 512;
constexpr int BT = B * T;  // 16384
}

// ---------------- scratch (static device arrays; no allocation) ----------------
__device__ __align__(128) __nv_bfloat16 g_X[2 * cfg::BT * cfg::C];       // [xl, xr]
__device__ __align__(128) __nv_bfloat16 g_w16[6 * cfg::C * cfg::C];      // lp1,rp1,lp2,rp2,lp3,rp3
__device__ __align__(128) __nv_bfloat16 g_h[4 * cfg::BT * cfg::C];       // proj outputs
__device__ __align__(128) __nv_bfloat16 g_Q[2 * cfg::BT * cfg::C];       // [Ql, Qr]
__device__ __align__(128) __nv_bfloat16 g_VT[2 * cfg::B * cfg::C * cfg::T]; // [VrT, VlT]
__device__ __align__(128) __nv_bfloat16 g_S [(size_t)cfg::B * cfg::T * cfg::T];
__device__ __align__(128) __nv_bfloat16 g_S2[(size_t)cfg::B * cfg::T * cfg::T];
__device__ __align__(128) __nv_bfloat16 g_P [2 * (size_t)cfg::B * cfg::T * cfg::T]; // [P1, P2]
__device__ __align__(128) __nv_bfloat16 g_F [2 * cfg::BT * cfg::C];      // [F1, F2]

struct P4 { const float* p[4]; };
struct DW2 { const float* w2[2]; const float* b2[2]; };

// ---------------- helpers ----------------
__device__ __forceinline__ uint32_t smem_u32(const void* p) {
    uint32_t a;
    asm("{ .reg .u64 t; cvta.to.shared.u64 t, %1; cvt.u32.u64 %0, t; }" : "=r"(a) : "l"(p));
    return a;
}

#define CP_ASYNC16(dst, src) \
    asm volatile("cp.async.cg.shared.global [%0], [%1], 16;" :: "r"(dst), "l"(src) : "memory")
#define CP_COMMIT() asm volatile("cp.async.commit_group;" ::: "memory")
#define CP_WAIT(n)  asm volatile("cp.async.wait_group %0;" :: "n"(n) : "memory")

#define LDSM4(r, addr) \
    asm volatile("ldmatrix.sync.aligned.m8n8.x4.shared.b16 {%0,%1,%2,%3}, [%4];" \
        : "=r"((r)[0]), "=r"((r)[1]), "=r"((r)[2]), "=r"((r)[3]) : "r"(addr))

#define MMA16816(c, a, b0, b1) \
    asm volatile("mma.sync.aligned.m16n8k16.row.col.f32.bf16.bf16.f32 " \
        "{%0,%1,%2,%3}, {%4,%5,%6,%7}, {%8,%9}, {%0,%1,%2,%3};" \
        : "+f"((c)[0]), "+f"((c)[1]), "+f"((c)[2]), "+f"((c)[3]) \
        : "r"((a)[0]), "r"((a)[1]), "r"((a)[2]), "r"((a)[3]), "r"(b0), "r"(b1))

#define SW128(o) ((o) ^ (((o) >> 3) & 0x70))

union BF8 { uint4 u; __nv_bfloat162 h2[4]; };

// ---------------- bf16 mma.sync GEMM (R10-proven mainloop; MODE2 staging de-conflicted) ----------------
template <int MODE>
__global__ __launch_bounds__(256, 2)
void k_gemmB(const __nv_bfloat16* __restrict__ A,
             const __nv_bfloat16* __restrict__ Bm,
             void* __restrict__ Cout, void* __restrict__ C2,
             P4 bias, P4 res,
             int K, int lda, int ldb, int ldc,
             long long sA, long long sB, long long sC,
             int zAmask, float scale) {
    constexpr int NS = 3;
    constexpr int STAGE = 2 * 128 * 128;
    extern __shared__ __align__(16) char dyn_raw[];
    const uint32_t sbase = smem_u32(dyn_raw);

    const int tid = threadIdx.x;
    const int lane = tid & 31, w = tid >> 5;
    const int wm = w & 3, wn = w >> 2;
    const int m0 = blockIdx.y * 128;
    const int n0 = blockIdx.x * 128;
    const int bz = blockIdx.z;
    A  += (size_t)(bz & zAmask) * sA;
    Bm += (size_t)bz * sB;

    const int nk = K >> 6;

    auto issue = [&](int kc, int s) {
        const uint32_t aB = sbase + s * STAGE;
        const uint32_t bB = aB + 16384;
        const __nv_bfloat16* Ag = A + (size_t)kc * 64;
        const __nv_bfloat16* Bg = Bm + (size_t)kc * 64;
#pragma unroll
        for (int i = 0; i < 4; i++) {
            int slot = tid + i * 256;
            int row = slot >> 3, v = slot & 7;
            CP_ASYNC16(aB + SW128(row * 128 + v * 16),
                       (const void*)(Ag + (size_t)(m0 + row) * lda + v * 8));
        }
#pragma unroll
        for (int i = 0; i < 4; i++) {
            int slot = tid + i * 256;
            int row = slot >> 3, v = slot & 7;
            CP_ASYNC16(bB + SW128(row * 128 + v * 16),
                       (const void*)(Bg + (size_t)(n0 + row) * ldb + v * 8));
        }
    };

    const uint32_t sxor = (uint32_t)(lane & 7) << 4;
    const uint32_t a_row = wm * 32 + (lane & 15);
    const uint32_t a_bc0 = (uint32_t)(lane >> 4) * 16;
    const uint32_t b_row = wn * 64 + (lane & 7) + ((lane >> 4) << 3);
    const uint32_t b_bc0 = (uint32_t)((lane >> 3) & 1) * 16;

    float acc[2][8][4];
#pragma unroll
    for (int mi = 0; mi < 2; mi++)
#pragma unroll
        for (int nj = 0; nj < 8; nj++)
#pragma unroll
            for (int e = 0; e < 4; e++) acc[mi][nj][e] = 0.f;

#pragma unroll
    for (int p = 0; p < NS - 1; p++) { issue(p, p); CP_COMMIT(); }
    CP_WAIT(NS - 2);
    __syncthreads();

    for (int kb = 0; kb < nk; kb++) {
        if (kb + NS - 1 < nk) issue(kb + NS - 1, (kb + NS - 1) % NS);
        CP_COMMIT();

        const uint32_t aB = sbase + (kb % NS) * STAGE;
        const uint32_t bB = aB + 16384;
#pragma unroll
        for (int ks = 0; ks < 4; ks++) {
            uint32_t af[2][4], bf[4][4];
            const uint32_t abc = ((uint32_t)ks * 32 + a_bc0) ^ sxor;
            const uint32_t bbc = ((uint32_t)ks * 32 + b_bc0) ^ sxor;
#pragma unroll
            for (int mi = 0; mi < 2; mi++)
                LDSM4(af[mi], aB + (a_row + mi * 16) * 128 + abc);
#pragma unroll
            for (int nb = 0; nb < 4; nb++)
                LDSM4(bf[nb], bB + (b_row + nb * 16) * 128 + bbc);
#pragma unroll
            for (int mi = 0; mi < 2; mi++)
#pragma unroll
                for (int nj = 0; nj < 8; nj++)
                    MMA16816(acc[mi][nj], af[mi], bf[nj >> 1][(nj & 1) * 2], bf[nj >> 1][(nj & 1) * 2 + 1]);
        }
        CP_WAIT(NS - 2);
        __syncthreads();
    }

    const size_t cb = (size_t)bz * sC;

    if constexpr (MODE == 2) { CP_WAIT(0); __syncthreads(); }
    unsigned short* sst = reinterpret_cast<unsigned short*>(dyn_raw);

    const float* bp = bias.p[bz & 3];
    const float* rp = res.p[bz & 3];

#pragma unroll
    for (int mi = 0; mi < 2; mi++) {
        const int r0 = m0 + wm * 32 + mi * 16 + (lane >> 2);
        const int rl = wm * 32 + mi * 16 + (lane >> 2);
#pragma unroll
        for (int nj = 0; nj < 8; nj++) {
            const int c = n0 + wn * 64 + nj * 8 + (lane & 3) * 2;
            const int cl = wn * 64 + nj * 8 + (lane & 3) * 2;
            float v0 = acc[mi][nj][0] * scale, v1 = acc[mi][nj][1] * scale;
            float v2 = acc[mi][nj][2] * scale, v3 = acc[mi][nj][3] * scale;
            if constexpr (MODE == 0) {
                if (bp) {
                    float b0 = bp[c], b1 = bp[c + 1];
                    v0 += b0; v1 += b1; v2 += b0; v3 += b1;
                }
                __nv_bfloat16* O = (__nv_bfloat16*)Cout;
                *reinterpret_cast<__nv_bfloat162*>(&O[cb + (size_t)r0 * ldc + c]) =
                    __floats2bfloat162_rn(v0, v1);
                *reinterpret_cast<__nv_bfloat162*>(&O[cb + (size_t)(r0 + 8) * ldc + c]) =
                    __floats2bfloat162_rn(v2, v3);
            } else if constexpr (MODE == 1) {
                float b0 = bp[c], b1 = bp[c + 1];
                float* O = (float*)Cout;
                size_t o1 = cb + (size_t)r0 * ldc + c;
                size_t o2 = cb + (size_t)(r0 + 8) * ldc + c;
                float2 r1 = *reinterpret_cast<const float2*>(&rp[(size_t)r0 * ldc + c]);
                float2 r2 = *reinterpret_cast<const float2*>(&rp[(size_t)(r0 + 8) * ldc + c]);
                *reinterpret_cast<float2*>(&O[o1]) = make_float2(v0 + b0 + r1.x, v1 + b1 + r1.y);
                *reinterpret_cast<float2*>(&O[o2]) = make_float2(v2 + b0 + r2.x, v3 + b1 + r2.y);
            } else {  // MODE 2: dual store; staging rows rotated by 2*(row>>3) shorts (mod 128)
                __nv_bfloat16* O = (__nv_bfloat16*)Cout;
                __nv_bfloat162 p1 = __floats2bfloat162_rn(v0, v1);
                __nv_bfloat162 p2 = __floats2bfloat162_rn(v2, v3);
                *reinterpret_cast<__nv_bfloat162*>(&O[cb + (size_t)r0 * ldc + c]) = p1;
                *reinterpret_cast<__nv_bfloat162*>(&O[cb + (size_t)(r0 + 8) * ldc + c]) = p2;
                const int sc1 = (cl + 2 * (rl >> 3)) & 127;
                const int sc2 = (cl + 2 * ((rl + 8) >> 3)) & 127;
                *reinterpret_cast<__nv_bfloat162*>(&sst[rl * 136 + sc1]) = p1;
                *reinterpret_cast<__nv_bfloat162*>(&sst[(rl + 8) * 136 + sc2]) = p2;
            }
        }
    }

    if constexpr (MODE == 2) {
        __syncthreads();
        __nv_bfloat16* O2 = (__nv_bfloat16*)C2;
        const int mm = (tid & 15) * 8;
        const int ln = tid & 15;               // == mm >> 3
#pragma unroll
        for (int it = 0; it < 8; it++) {
            const int nn = it * 16 + (tid >> 4);
            const int colp = (nn + 2 * ln) & 127;  // rotated column, constant over j
            unsigned short u[8];
#pragma unroll
            for (int j = 0; j < 8; j++) u[j] = sst[(mm + j) * 136 + colp];
            uint4 o;
            o.x = u[0] | ((uint32_t)u[1] << 16);
            o.y = u[2] | ((uint32_t)u[3] << 16);
            o.z = u[4] | ((uint32_t)u[5] << 16);
            o.w = u[6] | ((uint32_t)u[7] << 16);
            *reinterpret_cast<uint4*>(&O2[cb + (size_t)(n0 + nn) * ldc + m0 + mm]) = o;
        }
    }
}

// ---------------- elementwise / conversion kernels (separate launches — R13 merge regressed) ----------------
__global__ void k_f2bf_x(const float* __restrict__ xl, const float* __restrict__ xr,
                         __nv_bfloat16* __restrict__ out, int n4) {
    int i = blockIdx.x * blockDim.x + threadIdx.x;
    if (i < 2 * n4) {
        const float* s = (i < n4) ? xl : xr;
        int off = (i < n4) ? i : i - n4;
        float4 f = reinterpret_cast<const float4*>(s)[off];
        __nv_bfloat162* o = reinterpret_cast<__nv_bfloat162*>(out) + 2 * (size_t)i;
        o[0] = __floats2bfloat162_rn(f.x, f.y);
        o[1] = __floats2bfloat162_rn(f.z, f.w);
    }
}

__global__ void k_f2bf6(const float* s0, const float* s1, const float* s2,
                        const float* s3, const float* s4, const float* s5,
                        __nv_bfloat16* __restrict__ out) {
    int i = blockIdx.x * blockDim.x + threadIdx.x;
    int which = i >> 16, off = i & 65535;
    const float* s = which == 0 ? s0 : which == 1 ? s1 : which == 2 ? s2
                    : which == 3 ? s3 : which == 4 ? s4 : s5;
    float4 f = reinterpret_cast<const float4*>(s)[off];
    __nv_bfloat162* o = reinterpret_cast<__nv_bfloat162*>(out + ((size_t)which << 18));
    o[2 * off]     = __floats2bfloat162_rn(f.x, f.y);
    o[2 * off + 1] = __floats2bfloat162_rn(f.z, f.w);
}

// depthwise conv k=3: 8 channels x 4 t-positions per thread (sliding window)
__global__ void k_dwconv(const __nv_bfloat16* __restrict__ hbase,
                         __nv_bfloat16* __restrict__ qbase, DW2 dw) {
    const int side = blockIdx.y;
    const __nv_bfloat16* h = hbase + (size_t)side * cfg::BT * cfg::C;
    __nv_bfloat16* out = qbase + (size_t)side * cfg::BT * cfg::C;
    const float* w2 = dw.w2[side];
    const float* b2 = dw.b2[side];
    int i = blockIdx.x * blockDim.x + threadIdx.x;
    if (i >= (cfg::BT / 4) * (cfg::C / 8)) return;
    const int c8 = (i & (cfg::C / 8 - 1)) * 8;
    const int tq = i >> 6;
    const int b  = tq >> 9;
    const int t0 = (tq & 511) * 4;
    const size_t rbase = ((size_t)b * cfg::T + t0) * cfg::C + c8;

    BF8 r[6];
#pragma unroll
    for (int j = 0; j < 6; j++) {
        int t = t0 - 1 + j;
        if (t >= 0 && t < cfg::T)
            r[j].u = *reinterpret_cast<const uint4*>(h + rbase + (size_t)(j - 1) * cfg::C);
        else
            r[j].u = make_uint4(0, 0, 0, 0);
    }

    float4 wv[6];
#pragma unroll
    for (int k = 0; k < 6; k++) wv[k] = reinterpret_cast<const float4*>(w2 + c8 * 3)[k];
    const float* wf = reinterpret_cast<const float*>(wv);
    float4 bv0 = *reinterpret_cast<const float4*>(b2 + c8);
    float4 bv1 = *reinterpret_cast<const float4*>(b2 + c8 + 4);
    float bb[8] = {bv0.x, bv0.y, bv0.z, bv0.w, bv1.x, bv1.y, bv1.z, bv1.w};

#pragma unroll
    for (int k = 0; k < 4; k++) {
        BF8 o;
#pragma unroll
        for (int p = 0; p < 4; p++) {
            float2 pp = __bfloat1622float2(r[k].h2[p]);
            float2 cc = __bfloat1622float2(r[k + 1].h2[p]);
            float2 nn = __bfloat1622float2(r[k + 2].h2[p]);
            int j0 = 2 * p, j1 = 2 * p + 1;
            float v0 = pp.x * wf[j0 * 3 + 0] + cc.x * wf[j0 * 3 + 1] + nn.x * wf[j0 * 3 + 2] + bb[j0];
            float v1 = pp.y * wf[j1 * 3 + 0] + cc.y * wf[j1 * 3 + 1] + nn.y * wf[j1 * 3 + 2] + bb[j1];
            o.h2[p] = __floats2bfloat162_rn(v0, v1);
        }
        *reinterpret_cast<uint4*>(out + rbase + (size_t)k * cfg::C) = o.u;
    }
}

// depthwise conv k=3 + transpose: h[2+side] (B,T,C) -> g_VT[1-side] (B,C,T)
__global__ void k_dwconv_t(const __nv_bfloat16* __restrict__ hbase,
                           __nv_bfloat16* __restrict__ vtbase, DW2 dw) {
    __shared__ __nv_bfloat16 s[66][40];
    const int z = blockIdx.z;
    const int side = z >> 3, b = z & 7;
    const int t0 = blockIdx.x * 64, c0 = blockIdx.y * 32;
    const __nv_bfloat16* hb = hbase + (size_t)(2 + side) * cfg::BT * cfg::C
                                    + (size_t)b * cfg::T * cfg::C;
    __nv_bfloat16* outT = vtbase + (size_t)(1 - side) * cfg::B * cfg::C * cfg::T
                                 + (size_t)b * cfg::C * cfg::T;
    const int tid = threadIdx.x;
    for (int slot = tid; slot < 66 * 4; slot += 256) {
        int row = slot >> 2, q = slot & 3;
        int t = t0 + row - 1;
        uint4 val = make_uint4(0, 0, 0, 0);
        if (t >= 0 && t < cfg::T)
            val = *reinterpret_cast<const uint4*>(hb + (size_t)t * cfg::C + c0 + q * 8);
        *reinterpret_cast<uint4*>(&s[row][q * 8]) = val;
    }
    __syncthreads();

    const int c = tid >> 3;
    const int g = tid & 7;
    const int cg = c0 + c;
    const float w0 = dw.w2[side][cg * 3 + 0];
    const float w1 = dw.w2[side][cg * 3 + 1];
    const float w2v = dw.w2[side][cg * 3 + 2];
    const float bb = dw.b2[side][cg];

    BF8 o;
#pragma unroll
    for (int p = 0; p < 4; p++) {
        int tt0 = g * 8 + 2 * p, tt1 = tt0 + 1;
        float v0 = __bfloat162float(s[tt0][c]) * w0 + __bfloat162float(s[tt0 + 1][c]) * w1
                 + __bfloat162float(s[tt0 + 2][c]) * w2v + bb;
        float v1 = __bfloat162float(s[tt1][c]) * w0 + __bfloat162float(s[tt1 + 1][c]) * w1
                 + __bfloat162float(s[tt1 + 2][c]) * w2v + bb;
        o.h2[p] = __floats2bfloat162_rn(v0, v1);
    }
    *reinterpret_cast<uint4*>(outT + (size_t)cg * cfg::T + t0 + g * 8) = o.u;
}

// row softmax: uint4 load/store, shfl reductions
__global__ void k_softmax(const __nv_bfloat16* __restrict__ Sp,
                          const __nv_bfloat16* __restrict__ S2,
                          __nv_bfloat16* __restrict__ Pb) {
    const size_t row = blockIdx.x;
    const int y = blockIdx.y;
    const __nv_bfloat16* s = (y == 0 ? Sp : S2) + row * cfg::T;
    __nv_bfloat16* p = Pb + (size_t)y * cfg::B * cfg::T * cfg::T + row * cfg::T;
    const int tid = threadIdx.x;
    const int lane = tid & 31, wid = tid >> 5;

    BF8 in;
    in.u = *reinterpret_cast<const uint4*>(s + tid * 8);
    float v[8];
#pragma unroll
    for (int pq = 0; pq < 4; pq++) {
        float2 f = __bfloat1622float2(in.h2[pq]);
        v[2 * pq] = f.x; v[2 * pq + 1] = f.y;
    }

    float m = v[0];
#pragma unroll
    for (int j = 1; j < 8; j++) m = fmaxf(m, v[j]);
#pragma unroll
    for (int o = 16; o > 0; o >>= 1) m = fmaxf(m, __shfl_xor_sync(0xFFFFFFFFu, m, o));
    __shared__ float sm[8], ss[8];
    if (lane == 0) sm[wid] = m;
    __syncthreads();
    m = sm[0];
#pragma unroll
    for (int j = 1; j < 8; j++) m = fmaxf(m, sm[j]);

    float sum = 0.f;
#pragma unroll
    for (int j = 0; j < 8; j++) { v[j] = __expf(v[j] - m); sum += v[j]; }
#pragma unroll
    for (int o = 16; o > 0; o >>= 1) sum += __shfl_xor_sync(0xFFFFFFFFu, sum, o);
    if (lane == 0) ss[wid] = sum;
    __syncthreads();
    float tot = ss[0];
#pragma unroll
    for (int j = 1; j < 8; j++) tot += ss[j];
    const float inv = 1.f / tot;

    BF8 o;
#pragma unroll
    for (int pq = 0; pq < 4; pq++)
        o.h2[pq] = __floats2bfloat162_rn(v[2 * pq] * inv, v[2 * pq + 1] * inv);
    *reinterpret_cast<uint4*>(p + tid * 8) = o.u;
}

// ---------------- host ----------------
template <typename Tp>
static Tp* sym(const void* s) {
    void* p = nullptr;
    cudaGetSymbolAddress(&p, s);
    return reinterpret_cast<Tp*>(p);
}

extern "C" void kernel_launch(void* const* d_in, const int* in_sizes, int n_in,
                              void* d_out, int out_size) {
    using namespace cfg;
    const float* x_l    = (const float*)d_in[0];
    const float* x_r    = (const float*)d_in[1];
    const float* lp1_w1 = (const float*)d_in[2];  const float* lp1_b1 = (const float*)d_in[3];
    const float* lp1_w2 = (const float*)d_in[4];  const float* lp1_b2 = (const float*)d_in[5];
    const float* rp1_w1 = (const float*)d_in[6];  const float* rp1_b1 = (const float*)d_in[7];
    const float* rp1_w2 = (const float*)d_in[8];  const float* rp1_b2 = (const float*)d_in[9];
    const float* lp2_w1 = (const float*)d_in[10]; const float* lp2_b1 = (const float*)d_in[11];
    const float* lp2_w2 = (const float*)d_in[12]; const float* lp2_b2 = (const float*)d_in[13];
    const float* rp2_w1 = (const float*)d_in[14]; const float* rp2_b1 = (const float*)d_in[15];
    const float* rp2_w2 = (const float*)d_in[16]; const float* rp2_b2 = (const float*)d_in[17];
    const float* lp3_w  = (const float*)d_in[18]; const float* lp3_b  = (const float*)d_in[19];
    const float* rp3_w  = (const float*)d_in[20]; const float* rp3_b  = (const float*)d_in[21];

    __nv_bfloat16* X   = sym<__nv_bfloat16>(g_X);
    __nv_bfloat16* w16 = sym<__nv_bfloat16>(g_w16);
    __nv_bfloat16* h   = sym<__nv_bfloat16>(g_h);
    __nv_bfloat16* Q   = sym<__nv_bfloat16>(g_Q);
    __nv_bfloat16* VT  = sym<__nv_bfloat16>(g_VT);
    __nv_bfloat16* Sp  = sym<__nv_bfloat16>(g_S);
    __nv_bfloat16* S2  = sym<__nv_bfloat16>(g_S2);
    __nv_bfloat16* P   = sym<__nv_bfloat16>(g_P);
    __nv_bfloat16* F   = sym<__nv_bfloat16>(g_F);

    const int n  = BT * C;
    const int nw = C * C;
    const float scale = 0.04419417382415922f;  // 512^-0.5
    const int DSM = 3 * 2 * 128 * 128;         // 98304 B

    cudaFuncSetAttribute(k_gemmB<0>, cudaFuncAttributeMaxDynamicSharedMemorySize, DSM);
    cudaFuncSetAttribute(k_gemmB<1>, cudaFuncAttributeMaxDynamicSharedMemorySize, DSM);
    cudaFuncSetAttribute(k_gemmB<2>, cudaFuncAttributeMaxDynamicSharedMemorySize, DSM);

    P4 nob = {{nullptr, nullptr, nullptr, nullptr}};

    k_f2bf_x<<<(2 * (n / 4) + 255) / 256, 256>>>(x_l, x_r, X, n / 4);
    k_f2bf6<<<(6 * (nw / 4)) / 256, 256>>>(lp1_w1, rp1_w1, lp2_w1, rp2_w1, lp3_w, rp3_w, w16);

    // 4 projection GEMMs, one launch
    {
        P4 pb = {{lp1_b1, rp1_b1, lp2_b1, rp2_b1}};
        dim3 g(C / 128, BT / 128, 4);
        k_gemmB<0><<<g, 256, DSM>>>(X, w16, h, nullptr, pb, nob,
                                    C, C, C, C, (long long)n, (long long)nw, (long long)n,
                                    1, 1.f);
    }

    // dwconv Q + dwconv-transpose V
    {
        DW2 dq = {{lp1_w2, rp1_w2}, {lp1_b2, rp1_b2}};
        k_dwconv<<<dim3(((BT / 4) * (C / 8) + 255) / 256, 2), 256>>>(h, Q, dq);
        DW2 dv = {{lp2_w2, rp2_w2}, {lp2_b2, rp2_b2}};
        k_dwconv_t<<<dim3(T / 64, C / 32, 16), 256>>>(h, VT, dv);
    }

    // S = scale * Ql.Qr with dual store (S + S^T)
    {
        dim3 g(T / 128, T / 128, B);
        k_gemmB<2><<<g, 256, DSM>>>(Q, Q + n, Sp, S2, nob, nob,
                                    C, C, C, T,
                                    (long long)T * C, (long long)T * C, (long long)T * T,
                                    -1, scale);
    }

    // both softmaxes in one launch
    k_softmax<<<dim3(B * T, 2), 256>>>(Sp, S2, P);

    // F GEMMs
    {
        dim3 g(C / 128, T / 128, 16);
        k_gemmB<0><<<g, 256, DSM>>>(P, VT, F, nullptr, nob, nob,
                                    T, T, T, C,
                                    (long long)T * T, (long long)C * T, (long long)T * C,
                                    -1, 1.f);
    }

    // out GEMMs with residual
    {
        P4 ob = {{lp3_b, rp3_b, nullptr, nullptr}};
        P4 orr = {{x_l, x_r, nullptr, nullptr}};
        dim3 g(C / 128, BT / 128, 2);
        k_gemmB<1><<<g, 256, DSM>>>(F, w16 + 4 * nw, d_out, nullptr, ob, orr,
                                    C, C, C, C,
                                    (long long)n, (long long)nw, (long long)n,
                                    -1, 1.f);
    }
}